// round 2
// baseline (speedup 1.0000x reference)
#include <cuda_runtime.h>

#define BATCH   4
#define NPTS    8192
#define TOTAL   (BATCH * NPTS)      // 32768 points per array
#define TPP     8                   // query points per thread
#define PP      (TPP / 2)           // packed query pairs per thread
#define THREADS 256
#define CHUNK   (TPP * THREADS)     // 2048 query points per block
#define NCHUNK  (NPTS / CHUNK)      // 4
#define SLICE   512                 // candidates per block
#define NSLICE  (NPTS / SLICE)      // 16

// Scratch (__device__ globals — no allocation allowed):
// g_pts[a][i]      = (x, y, z, |p|^2)  (query-side loads)
// g_dup[a][2i+0]   = { (x,x), (y,y) }  (candidate-side, pre-duplicated for f32x2)
// g_dup[a][2i+1]   = { (z,z), (w,w) }
// g_minbits[dir][] = float-as-int running min (values clamped >= 0 -> int order valid)
__device__ float4     g_pts[2][TOTAL];
__device__ ulonglong2 g_dup[2][TOTAL * 2];
__device__ unsigned   g_minbits[2][TOTAL];

__device__ __forceinline__ unsigned long long pack2(float a, float b) {
    unsigned long long r;
    asm("mov.b64 %0, {%1, %2};" : "=l"(r) : "f"(a), "f"(b));
    return r;
}

#define FMA_F32X2(d, a, b, c) \
    asm("fma.rn.f32x2 %0, %1, %2, %3;" : "=l"(d) : "l"(a), "l"(b), "l"(c))

#define UNPACK_F32X2(lo, hi, v) \
    asm("mov.b64 {%0, %1}, %2;" : "=f"(lo), "=f"(hi) : "l"(v))

__global__ void prep_kernel(const float* __restrict__ p1,
                            const float* __restrict__ p2) {
    int i = blockIdx.x * blockDim.x + threadIdx.x;
    if (i >= TOTAL) return;
    {
        float x = p1[3 * i + 0], y = p1[3 * i + 1], z = p1[3 * i + 2];
        float w = fmaf(x, x, fmaf(y, y, z * z));
        g_pts[0][i] = make_float4(x, y, z, w);
        g_dup[0][2 * i + 0] = make_ulonglong2(pack2(x, x), pack2(y, y));
        g_dup[0][2 * i + 1] = make_ulonglong2(pack2(z, z), pack2(w, w));
    }
    {
        float x = p2[3 * i + 0], y = p2[3 * i + 1], z = p2[3 * i + 2];
        float w = fmaf(x, x, fmaf(y, y, z * z));
        g_pts[1][i] = make_float4(x, y, z, w);
        g_dup[1][2 * i + 0] = make_ulonglong2(pack2(x, x), pack2(y, y));
        g_dup[1][2 * i + 1] = make_ulonglong2(pack2(z, z), pack2(w, w));
    }
    g_minbits[0][i] = 0x7f800000u;  // +inf
    g_minbits[1][i] = 0x7f800000u;
}

// grid: (NCHUNK, NSLICE, 2*BATCH); z = (b << 1) | dir
// dist^2(q,c) = q.n + (c.n - 2*q.c); -2 folded into query regs, q.n added at end.
// Two query points packed per f32x2 lane-pair; candidate components duplicated.
__global__ __launch_bounds__(THREADS) void min_kernel() {
    __shared__ ulonglong2 sc[SLICE * 2];   // 16 KB

    const int z   = blockIdx.z;
    const int dir = z & 1;
    const int b   = z >> 1;

    const float4*     __restrict__ q = g_pts[dir] + b * NPTS;
    const ulonglong2* __restrict__ c =
        g_dup[dir ^ 1] + (b * NPTS + blockIdx.y * SLICE) * 2;
    unsigned* mb = g_minbits[dir] + b * NPTS;

    const int tid = threadIdx.x;

    #pragma unroll
    for (int j = 0; j < (SLICE * 2) / THREADS; j++)
        sc[tid + j * THREADS] = c[tid + j * THREADS];
    __syncthreads();

    const int pbase = blockIdx.x * CHUNK + tid;

    unsigned long long qx2[PP], qy2[PP], qz2[PP];
    float qn0[PP], qn1[PP], mnl[PP], mnh[PP];
    #pragma unroll
    for (int k = 0; k < PP; k++) {
        float4 a = q[pbase + (2 * k + 0) * THREADS];
        float4 d = q[pbase + (2 * k + 1) * THREADS];
        qx2[k] = pack2(-2.0f * a.x, -2.0f * d.x);
        qy2[k] = pack2(-2.0f * a.y, -2.0f * d.y);
        qz2[k] = pack2(-2.0f * a.z, -2.0f * d.z);
        qn0[k] = a.w;  qn1[k] = d.w;
        mnl[k] = 3.4e38f;  mnh[k] = 3.4e38f;
    }

    #pragma unroll 4
    for (int m = 0; m < SLICE; m++) {
        const ulonglong2 A = sc[2 * m + 0];  // (x,x),(y,y)  broadcast LDS.128
        const ulonglong2 B = sc[2 * m + 1];  // (z,z),(w,w)
        #pragma unroll
        for (int k = 0; k < PP; k++) {
            unsigned long long t;
            FMA_F32X2(t, qx2[k], A.x, B.y);   // -2qx*cx + cn   (x2)
            FMA_F32X2(t, qy2[k], A.y, t);
            FMA_F32X2(t, qz2[k], B.x, t);
            float lo, hi;
            UNPACK_F32X2(lo, hi, t);
            mnl[k] = fminf(mnl[k], lo);
            mnh[k] = fminf(mnh[k], hi);
        }
    }

    #pragma unroll
    for (int k = 0; k < PP; k++) {
        float v0 = fmaxf(mnl[k] + qn0[k], 0.0f);
        float v1 = fmaxf(mnh[k] + qn1[k], 0.0f);
        atomicMin((int*)&mb[pbase + (2 * k + 0) * THREADS], __float_as_int(v0));
        atomicMin((int*)&mb[pbase + (2 * k + 1) * THREADS], __float_as_int(v1));
    }
}

__global__ void reduce_kernel(float* __restrict__ out) {
    __shared__ float ssum[32];
    const int tid = threadIdx.x;
    const int* vals = (const int*)g_minbits;

    float s = 0.0f;
    for (int i = tid; i < 2 * TOTAL; i += blockDim.x)
        s += __int_as_float(vals[i]);

    #pragma unroll
    for (int o = 16; o; o >>= 1) s += __shfl_down_sync(0xffffffffu, s, o);
    if ((tid & 31) == 0) ssum[tid >> 5] = s;
    __syncthreads();
    if (tid < 32) {
        s = (tid < (int)(blockDim.x >> 5)) ? ssum[tid] : 0.0f;
        #pragma unroll
        for (int o = 16; o; o >>= 1) s += __shfl_down_sync(0xffffffffu, s, o);
        if (tid == 0) out[0] = s / (float)(BATCH * NPTS);
    }
}

extern "C" void kernel_launch(void* const* d_in, const int* in_sizes, int n_in,
                              void* d_out, int out_size) {
    const float* p1 = (const float*)d_in[0];
    const float* p2 = (const float*)d_in[1];

    prep_kernel<<<(TOTAL + 255) / 256, 256>>>(p1, p2);

    dim3 grid(NCHUNK, NSLICE, 2 * BATCH);
    min_kernel<<<grid, THREADS>>>();

    reduce_kernel<<<1, 1024>>>((float*)d_out);
}

// round 3
// speedup vs baseline: 1.2186x; 1.2186x over previous
#include <cuda_runtime.h>

#define BATCH   4
#define NPTS    8192
#define TOTAL   (BATCH * NPTS)

#define THREADS 256               // 8 warps
#define CPW     4                 // candidates per lane
#define CT      (8 * 32 * CPW)    // candidates per block = 1024
#define QT      256               // queries per block (staged in smem)
#define NQT     (NPTS / QT)       // 32
#define NCT     (NPTS / CT)       // 8

// Scratch (__device__ globals — no allocation allowed):
// g_pts[a][b*NPTS+i] = (x, y, z, |p|^2);  a=0 -> p1, a=1 -> p2
// g_minbits[dir][]   = positive-float-as-uint running min (u32 order == float order)
__device__ float4   g_pts[2][TOTAL];
__device__ unsigned g_minbits[2][TOTAL];

__global__ void prep_kernel(const float* __restrict__ p1,
                            const float* __restrict__ p2) {
    int i = blockIdx.x * blockDim.x + threadIdx.x;
    if (i >= TOTAL) return;
    float x = p1[3 * i + 0], y = p1[3 * i + 1], z = p1[3 * i + 2];
    g_pts[0][i] = make_float4(x, y, z, fmaf(x, x, fmaf(y, y, z * z)));
    x = p2[3 * i + 0]; y = p2[3 * i + 1]; z = p2[3 * i + 2];
    g_pts[1][i] = make_float4(x, y, z, fmaf(x, x, fmaf(y, y, z * z)));
    g_minbits[0][i] = 0x7f800000u;  // +inf
    g_minbits[1][i] = 0x7f800000u;
}

// Fused pass: each pair (q in p1, c in p2) evaluated once.
// d = (qn + cn) - 2*q.c ; feeds row-min (p1->p2) AND col-min (p2->p1).
// grid: (NQT, NCT, BATCH)
__global__ __launch_bounds__(THREADS) void min_kernel() {
    __shared__ float4   sq[QT];     // staged queries (4 KB)
    __shared__ unsigned srow[QT];   // per-block row mins (1 KB)

    const int b   = blockIdx.z;
    const int tid = threadIdx.x;
    const int wid = tid >> 5;
    const int lane = tid & 31;

    const float4* __restrict__ qs = g_pts[0] + b * NPTS + blockIdx.x * QT;
    const float4* __restrict__ cs = g_pts[1] + b * NPTS + blockIdx.y * CT;

    // Candidate registers: 4 per lane, -2 folded into coords, norm kept raw.
    float cx[CPW], cy[CPW], cz[CPW], cn[CPW], col[CPW];
    const int cbase = wid * (32 * CPW) + lane;
    #pragma unroll
    for (int k = 0; k < CPW; k++) {
        float4 c = cs[cbase + k * 32];
        cx[k] = -2.0f * c.x;
        cy[k] = -2.0f * c.y;
        cz[k] = -2.0f * c.z;
        cn[k] = c.w;
        col[k] = 3.4e38f;
    }

    for (int i = tid; i < QT; i += THREADS) {
        sq[i] = qs[i];
        srow[i] = 0x7f800000u;
    }
    __syncthreads();

    // Queries in chunks of 32; lane j owns the row-min of query j in the chunk.
    #pragma unroll 1
    for (int c0 = 0; c0 < QT; c0 += 32) {
        unsigned rowacc = 0x7f800000u;
        #pragma unroll 8
        for (int j = 0; j < 32; j++) {
            const float4 q = sq[c0 + j];   // warp-uniform broadcast LDS.128
            float d0, d1, d2, d3;
            {
                float t = fmaf(cz[0], q.z, cn[0] + q.w);
                t = fmaf(cy[0], q.y, t);
                d0 = fmaf(cx[0], q.x, t);
            }
            {
                float t = fmaf(cz[1], q.z, cn[1] + q.w);
                t = fmaf(cy[1], q.y, t);
                d1 = fmaf(cx[1], q.x, t);
            }
            {
                float t = fmaf(cz[2], q.z, cn[2] + q.w);
                t = fmaf(cy[2], q.y, t);
                d2 = fmaf(cx[2], q.x, t);
            }
            {
                float t = fmaf(cz[3], q.z, cn[3] + q.w);
                t = fmaf(cy[3], q.y, t);
                d3 = fmaf(cx[3], q.x, t);
            }
            col[0] = fminf(col[0], d0);
            col[1] = fminf(col[1], d1);
            col[2] = fminf(col[2], d2);
            col[3] = fminf(col[3], d3);
            float r = fminf(fminf(d0, d1), fminf(d2, d3));
            unsigned u = __reduce_min_sync(0xffffffffu, __float_as_uint(r));
            if (lane == j) rowacc = (u < rowacc) ? u : rowacc;
        }
        atomicMin(&srow[c0 + lane], rowacc);   // merge 8 warps, spread banks
    }
    __syncthreads();

    // Row mins -> global (p1 -> p2 direction)
    unsigned* rowg = g_minbits[0] + b * NPTS + blockIdx.x * QT;
    for (int i = tid; i < QT; i += THREADS)
        atomicMin(&rowg[i], srow[i]);

    // Col mins -> global (p2 -> p1 direction); clamp >=0 for u32 ordering
    unsigned* colg = g_minbits[1] + b * NPTS + blockIdx.y * CT;
    #pragma unroll
    for (int k = 0; k < CPW; k++)
        atomicMin(&colg[cbase + k * 32], __float_as_uint(fmaxf(col[k], 0.0f)));
}

__global__ void reduce_kernel(float* __restrict__ out) {
    __shared__ float ssum[32];
    const int tid = threadIdx.x;
    const unsigned* vals = (const unsigned*)g_minbits;

    float s = 0.0f;
    for (int i = tid; i < 2 * TOTAL; i += blockDim.x)
        s += __uint_as_float(vals[i]);

    #pragma unroll
    for (int o = 16; o; o >>= 1) s += __shfl_down_sync(0xffffffffu, s, o);
    if ((tid & 31) == 0) ssum[tid >> 5] = s;
    __syncthreads();
    if (tid < 32) {
        s = (tid < (int)(blockDim.x >> 5)) ? ssum[tid] : 0.0f;
        #pragma unroll
        for (int o = 16; o; o >>= 1) s += __shfl_down_sync(0xffffffffu, s, o);
        if (tid == 0) out[0] = s / (float)(BATCH * NPTS);
    }
}

extern "C" void kernel_launch(void* const* d_in, const int* in_sizes, int n_in,
                              void* d_out, int out_size) {
    const float* p1 = (const float*)d_in[0];
    const float* p2 = (const float*)d_in[1];

    prep_kernel<<<(TOTAL + 255) / 256, 256>>>(p1, p2);

    dim3 grid(NQT, NCT, BATCH);   // 32 x 8 x 4 = 1024 blocks
    min_kernel<<<grid, THREADS>>>();

    reduce_kernel<<<1, 1024>>>((float*)d_out);
}